// round 13
// baseline (speedup 1.0000x reference)
#include <cuda_runtime.h>
#include <math.h>

#define NN 8192
#define PAD 128            // padded-CSR slots per node; max in-degree ~66 << 128

// Scratch (allocation-free rule: device globals).
// g_cnt is zero at context init and is reset to zero by k_conv2 after use,
// so every launch (and every graph replay) starts from a clean state.
__device__ int   g_cnt   [NN];
__device__ int   g_colpad[NN * PAD];   // 4MB
__device__ float g_dinv  [NN];
__device__ float g_W1s   [NN * 16];    // dinv[n] * W1[n,:]
__device__ float g_h2s   [NN * 8];     // dinv[n] * h2[n,:]
__device__ float g_x2    [NN * 8];

// ---------------------------------------------------------------------------
// 1. one-pass padded-CSR fill (cnt doubles as in-degree afterwards)
__global__ void k_fill(const int* __restrict__ ei, int E) {
    int e = blockIdx.x * blockDim.x + threadIdx.x;
    if (e >= E) return;
    int s = ei[e];
    int d = ei[E + e];
    int pos = atomicAdd(&g_cnt[d], 1);
    g_colpad[d * PAD + pos] = s;
}

// 2. prep: dinv = rsqrt(deg+1); W1s[n,f] = dinv[n]*W1[n,f]
__global__ void k_prep(const float* __restrict__ W1) {
    int tid = blockIdx.x * blockDim.x + threadIdx.x;
    if (tid >= NN * 16) return;
    int n = tid >> 4;
    int f = tid & 15;
    float dn = rsqrtf((float)g_cnt[n] + 1.0f);
    if (f == 0) g_dinv[n] = dn;
    g_W1s[tid] = dn * W1[tid];
}

// 3. conv1: warp per node. lanes = 16 features x 2 edge-halves. Unrolled x4.
__global__ void k_conv1(const float* __restrict__ b1,
                        const float* __restrict__ W2) {
    int tid  = blockIdx.x * blockDim.x + threadIdx.x;
    int n    = tid >> 5;
    if (n >= NN) return;
    int lane = threadIdx.x & 31;
    int f    = lane & 15;
    int half = lane >> 4;                // 0 or 1

    float dn  = g_dinv[n];
    int   deg = g_cnt[n];
    const int* col = &g_colpad[n * PAD];

    // 4 independent accumulators, stride 8 over the edge list (2 halves x 4)
    float a0 = 0.0f, a1 = 0.0f, a2 = 0.0f, a3 = 0.0f;
    int e = half;
    for (; e + 6 < deg; e += 8) {
        int s0 = col[e];
        int s1 = col[e + 2];
        int s2 = col[e + 4];
        int s3 = col[e + 6];
        a0 += g_W1s[(size_t)s0 * 16 + f];
        a1 += g_W1s[(size_t)s1 * 16 + f];
        a2 += g_W1s[(size_t)s2 * 16 + f];
        a3 += g_W1s[(size_t)s3 * 16 + f];
    }
    for (; e < deg; e += 2) a0 += g_W1s[(size_t)col[e] * 16 + f];
    float acc = (a0 + a1) + (a2 + a3);
    acc += __shfl_xor_sync(0xffffffffu, acc, 16);          // combine halves
    float xf = fmaxf(dn * (acc + g_W1s[(size_t)n * 16 + f]) + b1[f], 0.0f);

    // h2[n,j] = sum_k xf(k) * W2[k,j]; store scaled by dinv[n]
    int j = f & 7;
    float h = 0.0f;
#pragma unroll
    for (int k = 0; k < 16; k++) {
        float xk = __shfl_sync(0xffffffffu, xf, k);        // lane k holds feat k
        h += xk * W2[k * 8 + j];
    }
    if (lane < 8) g_h2s[(size_t)n * 8 + j] = dn * h;
}

// 4. conv2: warp per node. lanes = 8 features x 4 edge-quarters.
//    Also resets g_cnt[n] = 0 after the last read (clean state for replay).
__global__ void k_conv2(const float* __restrict__ b2) {
    int tid  = blockIdx.x * blockDim.x + threadIdx.x;
    int n    = tid >> 5;
    if (n >= NN) return;
    int lane = threadIdx.x & 31;
    int j    = lane & 7;
    int q    = lane >> 3;                // 0..3

    float dn  = g_dinv[n];
    int   deg = g_cnt[n];
    const int* col = &g_colpad[n * PAD];
    float a0 = 0.0f, a1 = 0.0f;
    int e = q;
    for (; e + 4 < deg; e += 8) {
        int s0 = col[e];
        int s1 = col[e + 4];
        a0 += g_h2s[(size_t)s0 * 8 + j];
        a1 += g_h2s[(size_t)s1 * 8 + j];
    }
    for (; e < deg; e += 4) a0 += g_h2s[(size_t)col[e] * 8 + j];
    float acc = a0 + a1;
    acc += __shfl_xor_sync(0xffffffffu, acc, 8);
    acc += __shfl_xor_sync(0xffffffffu, acc, 16);
    float v = dn * (acc + g_h2s[(size_t)n * 8 + j]) + b2[j];
    if (lane < 8) g_x2[(size_t)n * 8 + j] = fmaxf(v, 0.0f);
    if (lane == 31) g_cnt[n] = 0;        // reset for next replay
}

// 5. scatter 1.0f at every directed edge (after the memset zero-fill)
__global__ void k_ones(const int* __restrict__ ei, int E,
                       float* __restrict__ out) {
    int e = blockIdx.x * blockDim.x + threadIdx.x;
    if (e >= E) return;
    int s = ei[e];
    int d = ei[E + e];
    out[(size_t)s * NN + d] = 1.0f;
}

// 6. orientation head: out[u,v] = sigmoid(ef @ Wfc + bfc); out[v,u] = 1 - it
__global__ void k_edgeout(const int* __restrict__ ue,
                          const float* __restrict__ Wfc,
                          const float* __restrict__ bfc,
                          float* __restrict__ out, int U) {
    int i = blockIdx.x * blockDim.x + threadIdx.x;
    if (i >= U) return;
    int u = ue[2 * i];
    int v = ue[2 * i + 1];
    float s = bfc[0];
#pragma unroll
    for (int f = 0; f < 8; f++) {
        s += g_x2[(size_t)u * 8 + f] * Wfc[f];
        s += g_x2[(size_t)v * 8 + f] * Wfc[8 + f];
    }
    float o = 1.0f / (1.0f + expf(-s));
    out[(size_t)u * NN + v] = o;
    out[(size_t)v * NN + u] = 1.0f - o;
}

extern "C" void kernel_launch(void* const* d_in, const int* in_sizes, int n_in,
                              void* d_out, int out_size) {
    const float* W1  = (const float*)d_in[1];
    const float* b1  = (const float*)d_in[2];
    const float* W2  = (const float*)d_in[3];
    const float* b2  = (const float*)d_in[4];
    const float* Wfc = (const float*)d_in[5];
    const float* bfc = (const float*)d_in[6];
    const int*   ei  = (const int*)d_in[7];
    const int*   ue  = (const int*)d_in[8];

    int E = in_sizes[7] / 2;
    int U = in_sizes[8] / 2;

    const int B = 256;

    // Pure single-stream pipeline: no stream/event creation (no alloc risk,
    // no fork overhead -- forks never overlapped on this scheduler anyway).
    cudaMemsetAsync(d_out, 0, (size_t)out_size * sizeof(float), 0);
    k_fill   <<<(E + B - 1) / B, B>>>(ei, E);
    k_prep   <<<(NN * 16 + B - 1) / B, B>>>(W1);
    k_conv1  <<<(NN * 32 + B - 1) / B, B>>>(b1, W2);
    k_conv2  <<<(NN * 32 + B - 1) / B, B>>>(b2);
    k_ones   <<<(E + B - 1) / B, B>>>(ei, E, (float*)d_out);
    k_edgeout<<<(U + B - 1) / B, B>>>(ue, Wfc, bfc, (float*)d_out, U);
}

// round 14
// speedup vs baseline: 1.0226x; 1.0226x over previous
#include <cuda_runtime.h>
#include <math.h>

#define NN 8192
#define PAD 128            // padded-CSR slots per node; max degree ~66 << 128

// Scratch (allocation-free rule: device globals).
// g_cnt / g_cnt2 are zero at context init and reset by k_conv2 / k_rowfill
// after use, so every launch (and graph replay) starts from a clean state.
__device__ int   g_cnt    [NN];        // in-degree  (dst-CSR)
__device__ int   g_cnt2   [NN];        // out-degree (src-CSR)
__device__ int   g_colpad [NN * PAD];  // dst-CSR: sources per destination
__device__ int   g_colpad2[NN * PAD];  // src-CSR: destinations per source
__device__ float g_dinv   [NN];
__device__ float g_W1s    [NN * 16];   // dinv[n] * W1[n,:]
__device__ float g_h2s    [NN * 8];    // dinv[n] * h2[n,:]
__device__ float g_x2     [NN * 8];

// ---------------------------------------------------------------------------
// 1. one-pass fill of BOTH padded CSRs (cnt/cnt2 double as degrees after)
__global__ void k_fill(const int* __restrict__ ei, int E) {
    int e = blockIdx.x * blockDim.x + threadIdx.x;
    if (e >= E) return;
    int s = ei[e];
    int d = ei[E + e];
    int p1 = atomicAdd(&g_cnt[d], 1);
    g_colpad[d * PAD + p1] = s;
    int p2 = atomicAdd(&g_cnt2[s], 1);
    g_colpad2[s * PAD + p2] = d;
}

// 2. prep: dinv = rsqrt(deg+1); W1s[n,f] = dinv[n]*W1[n,f]
__global__ void k_prep(const float* __restrict__ W1) {
    int tid = blockIdx.x * blockDim.x + threadIdx.x;
    if (tid >= NN * 16) return;
    int n = tid >> 4;
    int f = tid & 15;
    float dn = rsqrtf((float)g_cnt[n] + 1.0f);
    if (f == 0) g_dinv[n] = dn;
    g_W1s[tid] = dn * W1[tid];
}

// 3. conv1: warp per node. lanes = 16 features x 2 edge-halves. (R11 body)
__global__ void k_conv1(const float* __restrict__ b1,
                        const float* __restrict__ W2) {
    int tid  = blockIdx.x * blockDim.x + threadIdx.x;
    int n    = tid >> 5;
    if (n >= NN) return;
    int lane = threadIdx.x & 31;
    int f    = lane & 15;
    int half = lane >> 4;                // 0 or 1

    float dn  = g_dinv[n];
    int   deg = g_cnt[n];
    const int* col = &g_colpad[n * PAD];
    float acc = 0.0f;
    for (int e = half; e < deg; e += 2) {
        int s = col[e];
        acc += g_W1s[(size_t)s * 16 + f];
    }
    acc += __shfl_xor_sync(0xffffffffu, acc, 16);          // combine halves
    float xf = fmaxf(dn * (acc + g_W1s[(size_t)n * 16 + f]) + b1[f], 0.0f);

    // h2[n,j] = sum_k xf(k) * W2[k,j]; store scaled by dinv[n]
    int j = f & 7;
    float h = 0.0f;
#pragma unroll
    for (int k = 0; k < 16; k++) {
        float xk = __shfl_sync(0xffffffffu, xf, k);        // lane k holds feat k
        h += xk * W2[k * 8 + j];
    }
    if (lane < 8) g_h2s[(size_t)n * 8 + j] = dn * h;
}

// 4. conv2: warp per node. lanes = 8 features x 4 edge-quarters. (R11 body)
//    Resets g_cnt[n] = 0 after the last read (clean state for replay).
__global__ void k_conv2(const float* __restrict__ b2) {
    int tid  = blockIdx.x * blockDim.x + threadIdx.x;
    int n    = tid >> 5;
    if (n >= NN) return;
    int lane = threadIdx.x & 31;
    int j    = lane & 7;
    int q    = lane >> 3;                // 0..3

    float dn  = g_dinv[n];
    int   deg = g_cnt[n];
    const int* col = &g_colpad[n * PAD];
    float acc = 0.0f;
    for (int e = q; e < deg; e += 4) {
        int s = col[e];
        acc += g_h2s[(size_t)s * 8 + j];
    }
    acc += __shfl_xor_sync(0xffffffffu, acc, 8);
    acc += __shfl_xor_sync(0xffffffffu, acc, 16);
    float v = dn * (acc + g_h2s[(size_t)n * 8 + j]) + b2[j];
    if (lane < 8) g_x2[(size_t)n * 8 + j] = fmaxf(v, 0.0f);
    if (lane == 31) g_cnt[n] = 0;        // reset for next replay
}

// 5. FUSED output fill: one block per row. Stream the row as zeros with
//    __stwt (streaming stores, no L2 pollution), block-fence, then overwrite
//    the row's out-edge columns with 1.0f. Replaces memset + k_ones.
__global__ void __launch_bounds__(256)
k_rowfill(float* __restrict__ out) {
    int row = blockIdx.x;
    int t   = threadIdx.x;
    float4* rp = (float4*)(out + (size_t)row * NN);

    float4 z = make_float4(0.0f, 0.0f, 0.0f, 0.0f);
#pragma unroll
    for (int k = 0; k < 8; k++)                    // 2048 float4 per row
        __stwt(&rp[t + k * 256], z);
    __syncthreads();                               // order zeros before ones

    int odeg = g_cnt2[row];
    const int* col = &g_colpad2[row * PAD];
    if (t < odeg) out[(size_t)row * NN + col[t]] = 1.0f;
    if (t == 0) g_cnt2[row] = 0;                   // reset for next replay
}

// 6. orientation head: out[u,v] = sigmoid(ef @ Wfc + bfc); out[v,u] = 1 - it
__global__ void k_edgeout(const int* __restrict__ ue,
                          const float* __restrict__ Wfc,
                          const float* __restrict__ bfc,
                          float* __restrict__ out, int U) {
    int i = blockIdx.x * blockDim.x + threadIdx.x;
    if (i >= U) return;
    int u = ue[2 * i];
    int v = ue[2 * i + 1];
    float s = bfc[0];
#pragma unroll
    for (int f = 0; f < 8; f++) {
        s += g_x2[(size_t)u * 8 + f] * Wfc[f];
        s += g_x2[(size_t)v * 8 + f] * Wfc[8 + f];
    }
    float o = 1.0f / (1.0f + expf(-s));
    out[(size_t)u * NN + v] = o;
    out[(size_t)v * NN + u] = 1.0f - o;
}

extern "C" void kernel_launch(void* const* d_in, const int* in_sizes, int n_in,
                              void* d_out, int out_size) {
    const float* W1  = (const float*)d_in[1];
    const float* b1  = (const float*)d_in[2];
    const float* W2  = (const float*)d_in[3];
    const float* b2  = (const float*)d_in[4];
    const float* Wfc = (const float*)d_in[5];
    const float* bfc = (const float*)d_in[6];
    const int*   ei  = (const int*)d_in[7];
    const int*   ue  = (const int*)d_in[8];

    int E = in_sizes[7] / 2;
    int U = in_sizes[8] / 2;

    const int B = 256;

    // Single-stream pipeline; the dense write pass is ours (k_rowfill).
    k_fill   <<<(E + B - 1) / B, B>>>(ei, E);
    k_prep   <<<(NN * 16 + B - 1) / B, B>>>(W1);
    k_conv1  <<<(NN * 32 + B - 1) / B, B>>>(b1, W2);
    k_conv2  <<<(NN * 32 + B - 1) / B, B>>>(b2);
    k_rowfill<<<NN, B>>>((float*)d_out);
    k_edgeout<<<(U + B - 1) / B, B>>>(ue, Wfc, bfc, (float*)d_out, U);
}